// round 6
// baseline (speedup 1.0000x reference)
#include <cuda_runtime.h>
#include <cuda_bf16.h>

// MorletTransform via per-harmonic Goertzel recurrence (f32x2 packed lanes).
// Scheduling: 125 blocks x 1024 threads; each block processes 4 frames in
// independent 256-thread groups synchronized by NAMED barriers (bar.sync fg),
// so the 4 frame pipelines overlap and the grid forms one balanced wave
// (<=1 block/SM).
// Per frame (256 threads): pair = t&31 (harmonics 2p+1,2p+2 in f32x2 lanes),
// segpair = t>>5 -> two independent 64-sample Goertzel chains (ILP=2);
// all loop LDS are warp-broadcast (conflict-free).

#define TWO_PI_F 6.28318530717958647692f

__device__ __forceinline__ unsigned long long fma2(unsigned long long a,
                                                   unsigned long long b,
                                                   unsigned long long c) {
    unsigned long long d;
    asm("fma.rn.f32x2 %0, %1, %2, %3;" : "=l"(d) : "l"(a), "l"(b), "l"(c));
    return d;
}
__device__ __forceinline__ unsigned long long pk(float lo, float hi) {
    unsigned long long d;
    asm("mov.b64 %0, {%1, %2};" : "=l"(d) : "f"(lo), "f"(hi));
    return d;
}
__device__ __forceinline__ void upk(unsigned long long v, float& lo, float& hi) {
    asm("mov.b64 {%0, %1}, %2;" : "=f"(lo), "=f"(hi) : "l"(v));
}
__device__ __forceinline__ void bar_grp(int id) {
    asm volatile("bar.sync %0, 256;" :: "r"(id) : "memory");
}

__global__ void __launch_bounds__(1024, 1)
morlet_kernel(const float* __restrict__ audio,
              const float* __restrict__ f0,
              float* __restrict__ out_hd,
              float* __restrict__ out_amp,
              int frames) {
    const int tid = threadIdx.x;
    const int fg  = tid >> 8;          // frame group 0..3
    const int t   = tid & 255;         // thread within group
    const int f   = blockIdx.x * 4 + fg;
    if (f >= frames) return;           // whole group exits together

    __shared__ __align__(16) unsigned long long w2[4][1024]; // (w[n],w[n]) per frame
    __shared__ __align__(8) float sCth[4][64];
    __shared__ __align__(8) float sSth[4][64];

    // normalizer = 1/sqrt(pi*tp), tp = sr/half_bw = 16000
    const float normalizer = rsqrtf(3.14159265358979f * 16000.0f);
    const float inv_tp     = 1.0f / 16000.0f;
    const float inv_sr     = 1.0f / 16000.0f;
    const float f0v        = f0[f];

    // --- windowed frame: thread handles samples 4t .. 4t+3 ---
    {
        float4 a = ((const float4*)audio)[(size_t)f * 256 + t];
        int n = t * 4;
        float v[4] = {a.x, a.y, a.z, a.w};
        unsigned long long o[4];
        #pragma unroll
        for (int i = 0; i < 4; ++i) {
            float d  = (float)(n + i - 512);
            float wv = v[i] * (normalizer * __expf(-d * d * inv_tp));
            o[i] = pk(wv, wv);
        }
        ((ulonglong2*)w2[fg])[t * 2]     = make_ulonglong2(o[0], o[1]);
        ((ulonglong2*)w2[fg])[t * 2 + 1] = make_ulonglong2(o[2], o[3]);
    }

    // --- per-harmonic recurrence coefficients (accurate: cos error is
    //     amplified by 1/sin(theta) ~51 at k=1 -> __sincosf unsafe here) ---
    if (t < 64) {
        float fc = f0v * (float)(t + 1) * inv_sr;
        float s, c;
        sincosf(TWO_PI_F * fc, &s, &c);
        sCth[fg][t] = c;
        sSth[fg][t] = s;
    }
    bar_grp(fg);

    const int pair = t & 31;   // harmonics 2p+1, 2p+2
    const int sp   = t >> 5;   // segment pair: segments 2sp, 2sp+1

    float2 cth = ((const float2*)sCth[fg])[pair];
    float2 sth = ((const float2*)sSth[fg])[pair];
    const unsigned long long C2   = pk(2.0f * cth.x, 2.0f * cth.y);
    const unsigned long long NEG1 = pk(-1.0f, -1.0f);

    // --- two interleaved 64-sample Goertzel chains (ILP=2) ---
    const ulonglong2* wq0 = (const ulonglong2*)(w2[fg] + (2 * sp) * 64);
    const ulonglong2* wq1 = (const ulonglong2*)(w2[fg] + (2 * sp + 1) * 64);

    unsigned long long a1 = 0ull, a2 = 0ull;
    unsigned long long b1 = 0ull, b2 = 0ull;
    #pragma unroll 8
    for (int m = 0; m < 32; ++m) {
        ulonglong2 q = wq0[m];                        // broadcast LDS.128
        ulonglong2 r = wq1[m];
        unsigned long long t0 = fma2(NEG1, a2, q.x);
        unsigned long long s0 = fma2(C2, a1, t0);
        unsigned long long t1 = fma2(NEG1, a1, q.y);
        unsigned long long sn = fma2(C2, s0, t1);
        a2 = s0; a1 = sn;
        unsigned long long u0 = fma2(NEG1, b2, r.x);
        unsigned long long v0 = fma2(C2, b1, u0);
        unsigned long long u1 = fma2(NEG1, b1, r.y);
        unsigned long long vn = fma2(C2, v0, u1);
        b2 = v0; b1 = vn;
    }

    // --- finalize both chains into the global frame, sum in-register ---
    const float fcA = f0v * (float)(2 * pair + 1) * inv_sr;
    const float fcB = f0v * (float)(2 * pair + 2) * inv_sr;

    float reA = 0.0f, imA = 0.0f, reB = 0.0f, imB = 0.0f;
    #pragma unroll
    for (int c = 0; c < 2; ++c) {
        float x1A, x1B, x2A, x2B;
        if (c == 0) { upk(a1, x1A, x1B); upk(a2, x2A, x2B); }
        else        { upk(b1, x1A, x1B); upk(b2, x2A, x2B); }
        const float nend = (float)((2 * sp + c) * 64 + 63);
        {
            float yre = fmaf(-cth.x, x2A, x1A);
            float yim = sth.x * x2A;
            float p   = fcA * nend;
            p -= floorf(p);
            float sphi, cphi;
            __sincosf(TWO_PI_F * p, &sphi, &cphi);
            reA += yre * cphi + yim * sphi;
            imA += yim * cphi - yre * sphi;
        }
        {
            float yre = fmaf(-cth.y, x2B, x1B);
            float yim = sth.y * x2B;
            float p   = fcB * nend;
            p -= floorf(p);
            float sphi, cphi;
            __sincosf(TWO_PI_F * p, &sphi, &cphi);
            reB += yre * cphi + yim * sphi;
            imB += yim * cphi - yre * sphi;
        }
    }

    // --- overlay segment partials into the (now dead) w2 region ---
    bar_grp(fg);                       // all loop reads of w2[fg] done
    float2* sPart = (float2*)&w2[fg][0];   // [segpair][harmonic] (re,im), 4KB
    sPart[sp * 64 + 2 * pair]     = make_float2(reA, imA);
    sPart[sp * 64 + 2 * pair + 1] = make_float2(reB, imB);
    bar_grp(fg);

    // --- single-warp finish: lane l owns harmonics 2l+1, 2l+2 ---
    if (t < 32) {
        float r0 = 0.0f, i0 = 0.0f, r1 = 0.0f, i1 = 0.0f;
        #pragma unroll
        for (int s = 0; s < 8; ++s) {
            float2 p0 = sPart[s * 64 + 2 * t];
            float2 p1 = sPart[s * 64 + 2 * t + 1];
            r0 += p0.x; i0 += p0.y;
            r1 += p1.x; i1 += p1.y;
        }
        float mag0 = sqrtf(r0 * r0 + i0 * i0);
        float mag1 = sqrtf(r1 * r1 + i1 * i1);
        float fch0 = f0v * (float)(2 * t + 1) * inv_sr;
        float fch1 = f0v * (float)(2 * t + 2) * inv_sr;
        if (fch0 > 0.5f) mag0 = 0.0f;   // Nyquist mask
        if (fch1 > 0.5f) mag1 = 0.0f;

        float s = mag0 + mag1;
        #pragma unroll
        for (int o = 16; o > 0; o >>= 1)
            s += __shfl_xor_sync(0xffffffffu, s, o);   // amp in all lanes

        float inv = 1.0f / s;
        ((float2*)out_hd)[f * 32 + t] = make_float2(mag0 * inv, mag1 * inv);
        if (t == 0)
            out_amp[f] = fminf(fmaxf(s * 2.0f, 0.0f), 1.0f);
    }
}

extern "C" void kernel_launch(void* const* d_in, const int* in_sizes, int n_in,
                              void* d_out, int out_size) {
    const float* audio = (const float*)d_in[0];
    const float* f0    = (const float*)d_in[1];
    const int frames   = in_sizes[1];  // 2*250*1 = 500
    float* out         = (float*)d_out;
    morlet_kernel<<<(frames + 3) / 4, 1024>>>(audio, f0, out,
                                              out + (size_t)frames * 64, frames);
}

// round 8
// speedup vs baseline: 1.1123x; 1.1123x over previous
#include <cuda_runtime.h>
#include <cuda_bf16.h>

// MorletTransform via per-harmonic Goertzel recurrence (f32x2 packed lanes).
// Mapping: 256 threads/frame. Thread: quad = tid&15 -> harmonics 4q+1..4q+4
// as TWO f32x2 chains (ILP=2); segment = tid>>4 -> samples [seg*64, seg*64+64).
// Loop body: 1 LDS.128 (2 duplicated samples) + 8 FFMA2.
// Warp lanes span only 2 segments -> 2-address LDS (2 wavefronts max).
// Tail: partials overlay dead w2 region; race-free 2-warp finish
// (mag staged in dead sCth, full __syncthreads before cross-warp amp read).

#define TWO_PI_F 6.28318530717958647692f

__device__ __forceinline__ unsigned long long fma2(unsigned long long a,
                                                   unsigned long long b,
                                                   unsigned long long c) {
    unsigned long long d;
    asm("fma.rn.f32x2 %0, %1, %2, %3;" : "=l"(d) : "l"(a), "l"(b), "l"(c));
    return d;
}
__device__ __forceinline__ unsigned long long pk(float lo, float hi) {
    unsigned long long d;
    asm("mov.b64 %0, {%1, %2};" : "=l"(d) : "f"(lo), "f"(hi));
    return d;
}
__device__ __forceinline__ void upk(unsigned long long v, float& lo, float& hi) {
    asm("mov.b64 {%0, %1}, %2;" : "=f"(lo), "=f"(hi) : "l"(v));
}

__global__ void __launch_bounds__(256)
morlet_kernel(const float* __restrict__ audio,
              const float* __restrict__ f0,
              float* __restrict__ out_hd,
              float* __restrict__ out_amp) {
    const int f   = blockIdx.x;
    const int tid = threadIdx.x;

    __shared__ __align__(16) unsigned long long w2[1024]; // sample n -> (w[n],w[n]); 8KB
    __shared__ __align__(8) float sCth[64];
    __shared__ __align__(8) float sSth[64];
    __shared__ float sAmp[2];

    // normalizer = 1/sqrt(pi*tp), tp = sr/half_bw = 16000
    const float normalizer = rsqrtf(3.14159265358979f * 16000.0f);
    const float inv_tp     = 1.0f / 16000.0f;
    const float inv_sr     = 1.0f / 16000.0f;
    const float f0v        = f0[f];

    // --- windowed frame: thread handles samples 4*tid .. 4*tid+3 ---
    {
        float4 a = ((const float4*)audio)[(size_t)f * 256 + tid];
        int n = tid * 4;
        float v[4] = {a.x, a.y, a.z, a.w};
        unsigned long long o[4];
        #pragma unroll
        for (int i = 0; i < 4; ++i) {
            float d  = (float)(n + i - 512);
            float wv = v[i] * (normalizer * __expf(-d * d * inv_tp));
            o[i] = pk(wv, wv);
        }
        ((ulonglong2*)w2)[tid * 2]     = make_ulonglong2(o[0], o[1]);
        ((ulonglong2*)w2)[tid * 2 + 1] = make_ulonglong2(o[2], o[3]);
    }

    // --- per-harmonic recurrence coefficients (accurate: cos error is
    //     amplified by 1/sin(theta) ~51 at k=1 -> __sincosf unsafe here) ---
    if (tid < 64) {
        float fc = f0v * (float)(tid + 1) * inv_sr;
        float s, c;
        sincosf(TWO_PI_F * fc, &s, &c);
        sCth[tid] = c;
        sSth[tid] = s;
    }
    __syncthreads();

    const int quad = tid & 15;   // harmonics 4q+1 .. 4q+4
    const int seg  = tid >> 4;   // 16 segments of 64 samples

    float2 cthP = ((const float2*)sCth)[2 * quad];       // harmonics 4q+1, 4q+2
    float2 sthP = ((const float2*)sSth)[2 * quad];
    float2 cthQ = ((const float2*)sCth)[2 * quad + 1];   // harmonics 4q+3, 4q+4
    float2 sthQ = ((const float2*)sSth)[2 * quad + 1];
    const unsigned long long C2P  = pk(2.0f * cthP.x, 2.0f * cthP.y);
    const unsigned long long C2Q  = pk(2.0f * cthQ.x, 2.0f * cthQ.y);
    const unsigned long long NEG1 = pk(-1.0f, -1.0f);

    // --- Goertzel: two f32x2 chains over this thread's 64-sample segment ---
    const ulonglong2* wq = (const ulonglong2*)(w2 + seg * 64);

    unsigned long long p1 = 0ull, p2 = 0ull;  // chain P (harmonics 4q+1,4q+2)
    unsigned long long q1 = 0ull, q2 = 0ull;  // chain Q (harmonics 4q+3,4q+4)
    #pragma unroll
    for (int m = 0; m < 32; ++m) {
        ulonglong2 wv = wq[m];                         // 2 samples, duplicated
        unsigned long long t0 = fma2(NEG1, p2, wv.x);  // w - s_{n-2}
        unsigned long long s0 = fma2(C2P, p1, t0);
        unsigned long long u0 = fma2(NEG1, q2, wv.x);
        unsigned long long v0 = fma2(C2Q, q1, u0);
        unsigned long long t1 = fma2(NEG1, p1, wv.y);
        unsigned long long sn = fma2(C2P, s0, t1);
        unsigned long long u1 = fma2(NEG1, q1, wv.y);
        unsigned long long vn = fma2(C2Q, v0, u1);
        p2 = s0; p1 = sn;
        q2 = v0; q1 = vn;
    }

    // --- finalize 4 harmonics into the global frame ---
    const float nend = (float)(seg * 64 + 63);
    float re[4], im[4];
    {
        float x1A, x1B, x2A, x2B;
        upk(p1, x1A, x1B); upk(p2, x2A, x2B);
        float fcA = f0v * (float)(4 * quad + 1) * inv_sr;
        float fcB = f0v * (float)(4 * quad + 2) * inv_sr;
        float yre = fmaf(-cthP.x, x2A, x1A), yim = sthP.x * x2A;
        float p = fcA * nend; p -= floorf(p);
        float sphi, cphi; __sincosf(TWO_PI_F * p, &sphi, &cphi);
        re[0] = yre * cphi + yim * sphi; im[0] = yim * cphi - yre * sphi;
        yre = fmaf(-cthP.y, x2B, x1B); yim = sthP.y * x2B;
        p = fcB * nend; p -= floorf(p);
        __sincosf(TWO_PI_F * p, &sphi, &cphi);
        re[1] = yre * cphi + yim * sphi; im[1] = yim * cphi - yre * sphi;
    }
    {
        float x1A, x1B, x2A, x2B;
        upk(q1, x1A, x1B); upk(q2, x2A, x2B);
        float fcA = f0v * (float)(4 * quad + 3) * inv_sr;
        float fcB = f0v * (float)(4 * quad + 4) * inv_sr;
        float yre = fmaf(-cthQ.x, x2A, x1A), yim = sthQ.x * x2A;
        float p = fcA * nend; p -= floorf(p);
        float sphi, cphi; __sincosf(TWO_PI_F * p, &sphi, &cphi);
        re[2] = yre * cphi + yim * sphi; im[2] = yim * cphi - yre * sphi;
        yre = fmaf(-cthQ.y, x2B, x1B); yim = sthQ.y * x2B;
        p = fcB * nend; p -= floorf(p);
        __sincosf(TWO_PI_F * p, &sphi, &cphi);
        re[3] = yre * cphi + yim * sphi; im[3] = yim * cphi - yre * sphi;
    }

    // --- partials overlay the (now dead) w2 region: [seg][harmonic] (re,im) ---
    __syncthreads();                         // all loop reads of w2 complete
    float2* sPart = (float2*)&w2[0];         // 16*64 float2 = 8KB
    #pragma unroll
    for (int i = 0; i < 4; ++i)
        sPart[seg * 64 + 4 * quad + i] = make_float2(re[i], im[i]);
    __syncthreads();

    // --- finish stage 1: thread h (<64) reduces harmonic h over 16 segments,
    //     stages mag in (dead) sCth, warps publish partial amp sums ---
    if (tid < 64) {
        float r = 0.0f, i2 = 0.0f;
        #pragma unroll
        for (int s = 0; s < 16; ++s) {
            float2 pp = sPart[s * 64 + tid];
            r += pp.x; i2 += pp.y;
        }
        float mag = sqrtf(r * r + i2 * i2);
        float fch = f0v * (float)(tid + 1) * inv_sr;
        if (fch > 0.5f) mag = 0.0f;          // Nyquist mask
        sCth[tid] = mag;                     // stage for stage 2

        float s = mag;
        #pragma unroll
        for (int o = 16; o > 0; o >>= 1)
            s += __shfl_xor_sync(0xffffffffu, s, o);
        if ((tid & 31) == 0) sAmp[tid >> 5] = s;
    }
    __syncthreads();                         // cross-warp: sAmp + sCth visible

    // --- finish stage 2: normalize and store ---
    if (tid < 64) {
        float amp = sAmp[0] + sAmp[1];
        out_hd[f * 64 + tid] = sCth[tid] / amp;
        if (tid == 0)
            out_amp[f] = fminf(fmaxf(amp * 2.0f, 0.0f), 1.0f);
    }
}

extern "C" void kernel_launch(void* const* d_in, const int* in_sizes, int n_in,
                              void* d_out, int out_size) {
    const float* audio = (const float*)d_in[0];
    const float* f0    = (const float*)d_in[1];
    const int frames   = in_sizes[1];  // 2*250*1 = 500
    float* out         = (float*)d_out;
    morlet_kernel<<<frames, 256>>>(audio, f0, out, out + (size_t)frames * 64);
}